// round 1
// baseline (speedup 1.0000x reference)
#include <cuda_runtime.h>

// EmbeddingLoss: loss = N * sum_b sum_{n,m} pw[n]*pw[m] * (same ? 1-sim : relu(sim-0.5))
// with sim = E E^T per batch, E = emb.reshape(B, N, C) (raw row-major), N=4096, C=64.
// Symmetric in (n,m): compute upper triangle only, x2 off-diagonal.

namespace {
constexpr int NPIX  = 4096;     // 64*64
constexpr int CH    = 64;
constexpr int BATCH = 4;
constexpr int BM    = 128;      // tile rows == tile cols
constexpr int BK    = 32;       // k slab (2 slabs cover CH=64)
constexpr int TILES = NPIX / BM;                // 32
constexpr int TRI   = TILES * (TILES + 1) / 2;  // 528 upper-tri tiles
constexpr int SSTR  = BM + 1;   // smem row stride (129) -> conflict-free transpose store
constexpr float MARGIN = 0.5f;
}

__device__ double g_acc;
__device__ float  g_pw[BATCH * NPIX];

// Per-batch label histogram -> per-pixel weight 1/count. Also zeroes the accumulator.
__global__ void prep_kernel(const int* __restrict__ lab) {
    __shared__ int hist[16];
    const int b = blockIdx.x;
    const int t = threadIdx.x;
    if (t < 16) hist[t] = 0;
    if (b == 0 && t == 0) g_acc = 0.0;
    __syncthreads();
    const int* L = lab + b * NPIX;
    for (int n = t; n < NPIX; n += blockDim.x)
        atomicAdd(&hist[L[n] & 15], 1);   // labels are in [0,10)
    __syncthreads();
    for (int n = t; n < NPIX; n += blockDim.x)
        g_pw[b * NPIX + n] = 1.0f / (float)hist[L[n] & 15];
}

__global__ __launch_bounds__(256) void gram_kernel(const float* __restrict__ emb,
                                                   const int* __restrict__ lab) {
    __shared__ float As[BK][SSTR];   // As[k][row]  (transposed tile)
    __shared__ float Bs[BK][SSTR];   // Bs[k][col]
    __shared__ int   lrow[BM];
    __shared__ int   lcol[BM];
    __shared__ float prow[BM];
    __shared__ float pcol[BM];
    __shared__ float red[8];

    // Decode (batch, upper-tri tile (ti, tj))
    const int bx = blockIdx.x;
    const int b  = bx / TRI;
    int t = bx - b * TRI;
    int ti = 0;
    while (t >= TILES - ti) { t -= TILES - ti; ti++; }
    const int tj = ti + t;

    const int tid = threadIdx.x;
    const int tr  = tid >> 4;    // 0..15
    const int tc  = tid & 15;    // 0..15

    const float* Eb = emb + (size_t)b * NPIX * CH;
    const int*   Lb = lab + b * NPIX;
    const float* Pb = g_pw + b * NPIX;
    const int row0 = ti * BM, col0 = tj * BM;

    if (tid < BM) {
        lrow[tid] = Lb[row0 + tid];
        prow[tid] = Pb[row0 + tid];
    } else {
        const int u = tid - BM;
        lcol[u] = Lb[col0 + u];
        pcol[u] = Pb[col0 + u];
    }

    float acc[8][8];
#pragma unroll
    for (int i = 0; i < 8; i++)
#pragma unroll
        for (int j = 0; j < 8; j++) acc[i][j] = 0.0f;

    for (int kc = 0; kc < CH; kc += BK) {
        __syncthreads();
        // Load 128 rows x 32 k-cols of each operand, transposing into [k][row].
        // f = tid + 256p : r = f>>3 (row), c4 = (f&7)*4 (k within slab).
        // gmem: 8 lanes read 128B contiguous per row -> coalesced.
        // smem store bank = (c4+q+r) mod 32 covers all banks -> conflict-free.
#pragma unroll
        for (int p = 0; p < 4; p++) {
            const int f  = tid + p * 256;
            const int r  = f >> 3;
            const int c4 = (f & 7) << 2;
            const float4 va = *reinterpret_cast<const float4*>(
                Eb + (size_t)(row0 + r) * CH + kc + c4);
            As[c4 + 0][r] = va.x;
            As[c4 + 1][r] = va.y;
            As[c4 + 2][r] = va.z;
            As[c4 + 3][r] = va.w;
            const float4 vb = *reinterpret_cast<const float4*>(
                Eb + (size_t)(col0 + r) * CH + kc + c4);
            Bs[c4 + 0][r] = vb.x;
            Bs[c4 + 1][r] = vb.y;
            Bs[c4 + 2][r] = vb.z;
            Bs[c4 + 3][r] = vb.w;
        }
        __syncthreads();

        // 8x8 microtile, lane-interleaved: rows tr+16i (broadcast LDS),
        // cols tc+16j (stride-1 across lanes, conflict-free LDS).
#pragma unroll
        for (int k = 0; k < BK; k++) {
            float a[8], bb[8];
#pragma unroll
            for (int i = 0; i < 8; i++) a[i]  = As[k][tr + 16 * i];
#pragma unroll
            for (int j = 0; j < 8; j++) bb[j] = Bs[k][tc + 16 * j];
#pragma unroll
            for (int i = 0; i < 8; i++)
#pragma unroll
                for (int j = 0; j < 8; j++)
                    acc[i][j] = fmaf(a[i], bb[j], acc[i][j]);
        }
    }

    // Epilogue: per-pair loss, symmetry factor, weight.
    const bool diag = (ti == tj);
    float tsum = 0.0f;
#pragma unroll
    for (int i = 0; i < 8; i++) {
        const int rl = tr + 16 * i;
        const int ln = lrow[rl];
        const float pn = prow[rl];
        const int n = row0 + rl;
#pragma unroll
        for (int j = 0; j < 8; j++) {
            const int cl = tc + 16 * j;
            const int m  = col0 + cl;
            const float s = acc[i][j];
            const float v = (ln == lcol[cl]) ? (1.0f - s)
                                             : fmaxf(s - MARGIN, 0.0f);
            float w = pn * pcol[cl] * 2.0f;      // x2 for (n,m)+(m,n)
            if (diag) {
                if (m == n)      w *= 0.5f;      // diagonal counted once
                else if (m < n)  w = 0.0f;       // lower half skipped
            }
            tsum = fmaf(v, w, tsum);
        }
    }

    // Reduce 256 threads -> 1 double atomic per block.
#pragma unroll
    for (int o = 16; o > 0; o >>= 1)
        tsum += __shfl_xor_sync(0xffffffffu, tsum, o);
    if ((tid & 31) == 0) red[tid >> 5] = tsum;
    __syncthreads();
    if (tid == 0) {
        float bsum = 0.0f;
#pragma unroll
        for (int wv = 0; wv < 8; wv++) bsum += red[wv];
        atomicAdd(&g_acc, (double)bsum);
    }
}

__global__ void finalize_kernel(float* __restrict__ out) {
    out[0] = (float)(g_acc * (double)NPIX);
}

extern "C" void kernel_launch(void* const* d_in, const int* in_sizes, int n_in,
                              void* d_out, int out_size) {
    const float* emb = (const float*)d_in[0];
    const int*   lab = (const int*)d_in[1];
    float* out = (float*)d_out;

    prep_kernel<<<BATCH, 256>>>(lab);
    gram_kernel<<<BATCH * TRI, 256>>>(emb, lab);
    finalize_kernel<<<1, 1>>>(out);
}

// round 3
// speedup vs baseline: 2.7261x; 2.7261x over previous
#include <cuda_runtime.h>
#include <cuda_bf16.h>
#include <cstdint>

// EmbeddingLoss via mma.sync (HMMA) bf16 Gram matrix.
// loss = N * sum_b sum_{n,m} pw[n]*pw[m] * (same ? 1-sim : relu(sim-0.5)),
// sim = E E^T per batch, E = emb.reshape(B,N,C), N=4096, C=64, B=4.
// Upper-triangle tiles only (x2 off-diagonal). 128x128 tile per CTA,
// 8 warps each compute 64x32 via m16n8k16 bf16 atoms, fp32 accum in regs.

namespace {
constexpr int NPIX  = 4096;
constexpr int CH    = 64;
constexpr int BATCH = 4;
constexpr int BM    = 128;
constexpr int TILES = NPIX / BM;                 // 32
constexpr int TRI   = TILES * (TILES + 1) / 2;   // 528
constexpr float MARGIN = 0.5f;
}

__device__ double g_acc;
__device__ float  g_pw[BATCH * NPIX];
__device__ __nv_bfloat16 g_ebf[BATCH * NPIX * CH];  // bf16, per-row XOR-swizzled

__device__ __forceinline__ uint32_t smem_u32(const void* p) {
    uint32_t a;
    asm("{ .reg .u64 t; cvta.to.shared.u64 t, %1; cvt.u32.u64 %0, t; }"
        : "=r"(a) : "l"(p));
    return a;
}

__device__ __forceinline__ void ldsm_x4(uint32_t& r0, uint32_t& r1,
                                        uint32_t& r2, uint32_t& r3, uint32_t a) {
    asm volatile("ldmatrix.sync.aligned.m8n8.x4.shared.b16 {%0,%1,%2,%3}, [%4];"
                 : "=r"(r0), "=r"(r1), "=r"(r2), "=r"(r3) : "r"(a));
}

__device__ __forceinline__ void mma16816(float* d, const uint32_t* a,
                                         uint32_t b0, uint32_t b1) {
    asm volatile(
        "mma.sync.aligned.m16n8k16.row.col.f32.bf16.bf16.f32 "
        "{%0,%1,%2,%3}, {%4,%5,%6,%7}, {%8,%9}, {%0,%1,%2,%3};"
        : "+f"(d[0]), "+f"(d[1]), "+f"(d[2]), "+f"(d[3])
        : "r"(a[0]), "r"(a[1]), "r"(a[2]), "r"(a[3]), "r"(b0), "r"(b1));
}

// swizzled byte offset of (row R, 16B-chunk c) in a [rows x 64bf16] tile
__device__ __forceinline__ uint32_t sw_off(int R, int c) {
    return (uint32_t)(R * 128 + ((c ^ (R & 7)) << 4));
}

// ---------------- prep: per-warp histograms -> per-pixel weight -------------
__global__ void prep_kernel(const int* __restrict__ lab) {
    __shared__ int hist[8][16];
    const int b = blockIdx.x, t = threadIdx.x, w = t >> 5;
    if (t < 128) hist[t >> 4][t & 15] = 0;
    if (b == 0 && t == 0) g_acc = 0.0;
    __syncthreads();
    const int* L = lab + b * NPIX;
    for (int n = t; n < NPIX; n += 256) atomicAdd(&hist[w][L[n] & 15], 1);
    __syncthreads();
    if (t < 16) {
        int s = 0;
#pragma unroll
        for (int i = 0; i < 8; i++) s += hist[i][t];
        hist[0][t] = s;
    }
    __syncthreads();
    for (int n = t; n < NPIX; n += 256)
        g_pw[b * NPIX + n] = 1.0f / (float)hist[0][L[n] & 15];
}

// ---------------- convert fp32 -> bf16, XOR swizzle baked into gmem ---------
__global__ void conv_kernel(const float* __restrict__ emb) {
    const int q = blockIdx.x * blockDim.x + threadIdx.x;
    if (q >= BATCH * NPIX * CH / 4) return;
    const int c4 = (q & 15) * 4;
    const int n  = (q >> 4) & (NPIX - 1);
    const float4 v = reinterpret_cast<const float4*>(emb)[q];
    const int chunk = c4 >> 3;
    const int dcol  = ((chunk ^ (n & 7)) << 3) + (c4 & 7);
    __nv_bfloat16* dst = g_ebf + ((size_t)(q >> 4)) * CH + dcol;
    __nv_bfloat162* d2 = reinterpret_cast<__nv_bfloat162*>(dst);
    d2[0] = __nv_bfloat162(__float2bfloat16(v.x), __float2bfloat16(v.y));
    d2[1] = __nv_bfloat162(__float2bfloat16(v.z), __float2bfloat16(v.w));
}

// ---------------- main: HMMA Gram + register epilogue -----------------------
__global__ __launch_bounds__(256) void gram_kernel(const int* __restrict__ lab) {
    __shared__ __align__(16) __nv_bfloat16 Asm[BM * CH];   // 16KB
    __shared__ __align__(16) __nv_bfloat16 Bsm[BM * CH];   // 16KB
    __shared__ int   lrow[BM], lcol[BM];
    __shared__ float prow[BM], pcol[BM];
    __shared__ float red[8];

    const int bx = blockIdx.x;
    const int b  = bx / TRI;
    int t = bx - b * TRI;
    int ti = 0;
    while (t >= TILES - ti) { t -= TILES - ti; ti++; }
    const int tj = ti + t;
    const int row0 = ti * BM, col0 = tj * BM;

    const int tid = threadIdx.x;
    const int wid = tid >> 5;
    const int lid = tid & 31;
    const int wr  = wid & 1;    // row half (64 rows)
    const int wc  = wid >> 1;   // col quarter (32 cols)

    // tile copies: pre-swizzled bf16 -> straight 16KB copies
    {
        const uint4* srcA = reinterpret_cast<const uint4*>(
            g_ebf + ((size_t)(b * NPIX + row0)) * CH);
        const uint4* srcB = reinterpret_cast<const uint4*>(
            g_ebf + ((size_t)(b * NPIX + col0)) * CH);
        uint4* dA = reinterpret_cast<uint4*>(Asm);
        uint4* dB = reinterpret_cast<uint4*>(Bsm);
#pragma unroll
        for (int p = 0; p < 4; p++) {
            dA[tid + 256 * p] = srcA[tid + 256 * p];
            dB[tid + 256 * p] = srcB[tid + 256 * p];
        }
    }
    if (tid < BM) {
        lrow[tid] = lab[b * NPIX + row0 + tid];
        prow[tid] = g_pw[b * NPIX + row0 + tid];
    } else {
        const int u = tid - BM;
        lcol[u] = lab[b * NPIX + col0 + u];
        pcol[u] = g_pw[b * NPIX + col0 + u];
    }
    __syncthreads();

    const uint32_t a_base = smem_u32(Asm);
    const uint32_t b_base = smem_u32(Bsm);

    float acc[4][4][4];
#pragma unroll
    for (int i = 0; i < 4; i++)
#pragma unroll
        for (int j = 0; j < 4; j++)
#pragma unroll
            for (int e = 0; e < 4; e++) acc[i][j][e] = 0.0f;

    // ldmatrix address components (constant across k-steps except chunk)
    const int aR = 64 * wr + (lid & 15);   // A logical row for this lane
    const int bR = 32 * wc + (lid & 15);   // B' logical row (n) for this lane
    const int hi = lid >> 4;               // 0/1 -> k-chunk select within atom

#pragma unroll
    for (int ks = 0; ks < 4; ks++) {       // K = 64, 16 per step
        const int ck = ks * 2 + hi;        // 16B chunk index for this lane
        uint32_t a[4][4];
#pragma unroll
        for (int i = 0; i < 4; i++) {
            const int R = aR + 16 * i;
            ldsm_x4(a[i][0], a[i][1], a[i][2], a[i][3], a_base + sw_off(R, ck));
        }
        uint32_t bb[2][4];                 // [pair p][reg]; atoms: p*2 + sel
#pragma unroll
        for (int p = 0; p < 2; p++) {
            const int R = bR + 16 * p;
            ldsm_x4(bb[p][0], bb[p][1], bb[p][2], bb[p][3], b_base + sw_off(R, ck));
        }
        // B atom j: j=0:{bb0[0],bb0[2]} j=1:{bb0[1],bb0[3]} j=2:{bb1[0],bb1[2]} j=3:{bb1[1],bb1[3]}
#pragma unroll
        for (int i = 0; i < 4; i++) {
#pragma unroll
            for (int j = 0; j < 4; j++) {
                const uint32_t b0 = bb[j >> 1][j & 1];
                const uint32_t b1 = bb[j >> 1][(j & 1) + 2];
                mma16816(acc[i][j], a[i], b0, b1);
            }
        }
    }

    // ---------------- epilogue (register-resident accumulators) -------------
    const bool diag = (ti == tj);
    const int gr = lid >> 2;
    const int qc = (lid & 3) * 2;
    float tsum = 0.0f;
#pragma unroll
    for (int i = 0; i < 4; i++) {
        const int rl0 = 64 * wr + 16 * i + gr;
        const int rl1 = rl0 + 8;
        const int  ln0 = lrow[rl0], ln1 = lrow[rl1];
        const float pn0 = prow[rl0], pn1 = prow[rl1];
#pragma unroll
        for (int j = 0; j < 4; j++) {
            const int cl = 32 * wc + 8 * j + qc;
            const int  lc0 = lcol[cl],  lc1 = lcol[cl + 1];
            const float pc0 = pcol[cl], pc1 = pcol[cl + 1];
#pragma unroll
            for (int e = 0; e < 4; e++) {
                const int rl = (e < 2) ? rl0 : rl1;
                const int ln = (e < 2) ? ln0 : ln1;
                const float pn = (e < 2) ? pn0 : pn1;
                const int cc = cl + (e & 1);
                const int lc = (e & 1) ? lc1 : lc0;
                const float pc = (e & 1) ? pc1 : pc0;
                const float s = acc[i][j][e];
                const float v = (ln == lc) ? (1.0f - s)
                                           : fmaxf(s - MARGIN, 0.0f);
                float w = pn * pc * 2.0f;
                if (diag) {
                    const int n = row0 + rl, m = col0 + cc;
                    if (m == n)     w *= 0.5f;
                    else if (m < n) w = 0.0f;
                }
                tsum = fmaf(v, w, tsum);
            }
        }
    }

#pragma unroll
    for (int o = 16; o > 0; o >>= 1)
        tsum += __shfl_xor_sync(0xffffffffu, tsum, o);
    if (lid == 0) red[wid] = tsum;
    __syncthreads();
    if (tid == 0) {
        float bsum = 0.0f;
#pragma unroll
        for (int wv = 0; wv < 8; wv++) bsum += red[wv];
        atomicAdd(&g_acc, (double)bsum);
    }
}

__global__ void finalize_kernel(float* __restrict__ out) {
    out[0] = (float)(g_acc * (double)NPIX);
}

extern "C" void kernel_launch(void* const* d_in, const int* in_sizes, int n_in,
                              void* d_out, int out_size) {
    const float* emb = (const float*)d_in[0];
    const int*   lab = (const int*)d_in[1];
    float* out = (float*)d_out;

    prep_kernel<<<BATCH, 256>>>(lab);
    conv_kernel<<<(BATCH * NPIX * CH / 4 + 255) / 256, 256>>>(emb);
    gram_kernel<<<BATCH * TRI, 256>>>(lab);
    finalize_kernel<<<1, 1>>>(out);
}

// round 4
// speedup vs baseline: 3.0068x; 1.1030x over previous
#include <cuda_runtime.h>
#include <cuda_bf16.h>
#include <cstdint>

// EmbeddingLoss via mma.sync (HMMA) bf16 Gram matrix. 2-kernel pipeline:
//   K1: prep (label hist -> weights) + fp32->bf16 swizzled convert (fused)
//   K2: 128x128 Gram tiles (upper triangle, x2 off-diag) + epilogue + last-block finalize

namespace {
constexpr int NPIX  = 4096;
constexpr int CH    = 64;
constexpr int BATCH = 4;
constexpr int BM    = 128;
constexpr int TILES = NPIX / BM;                 // 32
constexpr int TRI   = TILES * (TILES + 1) / 2;   // 528
constexpr int GRID_GRAM = BATCH * TRI;           // 2112
constexpr int CONV_BLOCKS = BATCH * NPIX * CH / 4 / 256;  // 1024
constexpr float MARGIN = 0.5f;
}

__device__ double   g_acc;
__device__ unsigned g_done;
__device__ float    g_pw[BATCH * NPIX];
__device__ __nv_bfloat16 g_ebf[BATCH * NPIX * CH];  // bf16, per-row XOR-swizzled

__device__ __forceinline__ uint32_t smem_u32(const void* p) {
    uint32_t a;
    asm("{ .reg .u64 t; cvta.to.shared.u64 t, %1; cvt.u32.u64 %0, t; }"
        : "=r"(a) : "l"(p));
    return a;
}
__device__ __forceinline__ void ldsm_x4(uint32_t& r0, uint32_t& r1,
                                        uint32_t& r2, uint32_t& r3, uint32_t a) {
    asm volatile("ldmatrix.sync.aligned.m8n8.x4.shared.b16 {%0,%1,%2,%3}, [%4];"
                 : "=r"(r0), "=r"(r1), "=r"(r2), "=r"(r3) : "r"(a));
}
__device__ __forceinline__ void mma16816(float* d, const uint32_t* a,
                                         uint32_t b0, uint32_t b1) {
    asm volatile(
        "mma.sync.aligned.m16n8k16.row.col.f32.bf16.bf16.f32 "
        "{%0,%1,%2,%3}, {%4,%5,%6,%7}, {%8,%9}, {%0,%1,%2,%3};"
        : "+f"(d[0]), "+f"(d[1]), "+f"(d[2]), "+f"(d[3])
        : "r"(a[0]), "r"(a[1]), "r"(a[2]), "r"(a[3]), "r"(b0), "r"(b1));
}
__device__ __forceinline__ uint32_t sw_off(int R, int c) {
    return (uint32_t)(R * 128 + ((c ^ (R & 7)) << 4));
}

// ---------------- K1: fused prep + convert ----------------------------------
__global__ __launch_bounds__(256) void prep_conv_kernel(const float* __restrict__ emb,
                                                        const int* __restrict__ lab) {
    const int bx = blockIdx.x, tid = threadIdx.x;
    if (bx < CONV_BLOCKS) {
        // fp32 -> bf16 with per-row XOR-16B-chunk swizzle baked into gmem layout
        const int q = bx * 256 + tid;
        const int c4 = (q & 15) * 4;
        const int n  = (q >> 4) & (NPIX - 1);
        const float4 v = reinterpret_cast<const float4*>(emb)[q];
        const int chunk = c4 >> 3;
        const int dcol  = ((chunk ^ (n & 7)) << 3) + (c4 & 7);
        __nv_bfloat16* dst = g_ebf + ((size_t)(q >> 4)) * CH + dcol;
        __nv_bfloat162* d2 = reinterpret_cast<__nv_bfloat162*>(dst);
        d2[0] = __nv_bfloat162(__float2bfloat16(v.x), __float2bfloat16(v.y));
        d2[1] = __nv_bfloat162(__float2bfloat16(v.z), __float2bfloat16(v.w));
    } else {
        // per-batch label histogram -> per-pixel weight 1/count
        __shared__ int hist[8][16];
        const int b = bx - CONV_BLOCKS;
        const int w = tid >> 5;
        if (tid < 128) hist[tid >> 4][tid & 15] = 0;
        if (b == 0 && tid == 0) { g_acc = 0.0; g_done = 0u; }
        __syncthreads();
        const int* L = lab + b * NPIX;
        for (int n = tid; n < NPIX; n += 256) atomicAdd(&hist[w][L[n] & 15], 1);
        __syncthreads();
        if (tid < 16) {
            int s = 0;
#pragma unroll
            for (int i = 0; i < 8; i++) s += hist[i][tid];
            hist[0][tid] = s;
        }
        __syncthreads();
        for (int n = tid; n < NPIX; n += 256)
            g_pw[b * NPIX + n] = 1.0f / (float)hist[0][L[n] & 15];
    }
}

// ---------------- K2: HMMA Gram + epilogue + finalize ------------------------
__global__ __launch_bounds__(256) void gram_kernel(const int* __restrict__ lab,
                                                   float* __restrict__ out) {
    __shared__ __align__(16) __nv_bfloat16 Asm[BM * CH];   // 16KB
    __shared__ __align__(16) __nv_bfloat16 Bsm[BM * CH];   // 16KB
    __shared__ int   lrow[BM], lcol[BM];
    __shared__ float prow2[BM], pcol[BM];   // prow2 = 2*pw (symmetry factor folded)
    __shared__ float red[8];

    const int bx = blockIdx.x;
    const int b  = bx / TRI;
    int t = bx - b * TRI;
    int ti = 0;
    while (t >= TILES - ti) { t -= TILES - ti; ti++; }
    const int tj = ti + t;
    const int row0 = ti * BM, col0 = tj * BM;
    const bool diag = (ti == tj);

    const int tid = threadIdx.x;
    const int wid = tid >> 5;
    const int lid = tid & 31;
    const int wr  = wid & 1;
    const int wc  = wid >> 1;

    // tile copies: pre-swizzled bf16 -> straight 16KB copies (B reuses A if diag)
    {
        const uint4* srcA = reinterpret_cast<const uint4*>(
            g_ebf + ((size_t)(b * NPIX + row0)) * CH);
        uint4* dA = reinterpret_cast<uint4*>(Asm);
#pragma unroll
        for (int p = 0; p < 4; p++) dA[tid + 256 * p] = srcA[tid + 256 * p];
        if (!diag) {
            const uint4* srcB = reinterpret_cast<const uint4*>(
                g_ebf + ((size_t)(b * NPIX + col0)) * CH);
            uint4* dB = reinterpret_cast<uint4*>(Bsm);
#pragma unroll
            for (int p = 0; p < 4; p++) dB[tid + 256 * p] = srcB[tid + 256 * p];
        }
    }
    if (tid < BM) {
        lrow[tid]  = lab[b * NPIX + row0 + tid];
        prow2[tid] = 2.0f * g_pw[b * NPIX + row0 + tid];
    } else {
        const int u = tid - BM;
        lcol[u] = lab[b * NPIX + col0 + u];
        pcol[u] = g_pw[b * NPIX + col0 + u];
    }
    __syncthreads();

    const uint32_t a_base = smem_u32(Asm);
    const uint32_t b_base = diag ? a_base : smem_u32(Bsm);

    float acc[4][4][4];
#pragma unroll
    for (int i = 0; i < 4; i++)
#pragma unroll
        for (int j = 0; j < 4; j++)
#pragma unroll
            for (int e = 0; e < 4; e++) acc[i][j][e] = 0.0f;

    const int aR = 64 * wr + (lid & 15);
    const int bR = 32 * wc + (lid & 15);
    const int hi = lid >> 4;

#pragma unroll
    for (int ks = 0; ks < 4; ks++) {
        const int ck = ks * 2 + hi;
        uint32_t a[4][4];
#pragma unroll
        for (int i = 0; i < 4; i++) {
            const int R = aR + 16 * i;
            ldsm_x4(a[i][0], a[i][1], a[i][2], a[i][3], a_base + sw_off(R, ck));
        }
        uint32_t bb[2][4];
#pragma unroll
        for (int p = 0; p < 2; p++) {
            const int R = bR + 16 * p;
            ldsm_x4(bb[p][0], bb[p][1], bb[p][2], bb[p][3], b_base + sw_off(R, ck));
        }
#pragma unroll
        for (int i = 0; i < 4; i++)
#pragma unroll
            for (int j = 0; j < 4; j++)
                mma16816(acc[i][j], a[i], bb[j >> 1][j & 1], bb[j >> 1][(j & 1) + 2]);
    }

    // ---------------- epilogue --------------------------------------------
    const int gr = lid >> 2;
    const int qc = (lid & 3) * 2;
    float tsum = 0.0f;

    if (!diag) {
        // hot path: rowsum = sum_cols pc * v ; tsum += pn2 * rowsum
#pragma unroll
        for (int i = 0; i < 4; i++) {
            const int rl0 = 64 * wr + 16 * i + gr, rl1 = rl0 + 8;
            const int  ln0 = lrow[rl0], ln1 = lrow[rl1];
            float rs0 = 0.0f, rs1 = 0.0f;
#pragma unroll
            for (int j = 0; j < 4; j++) {
                const int cl = 32 * wc + 8 * j + qc;
                const int  lc0 = lcol[cl],  lc1 = lcol[cl + 1];
                const float pc0 = pcol[cl], pc1 = pcol[cl + 1];
                const float s0 = acc[i][j][0], s1 = acc[i][j][1];
                const float s2 = acc[i][j][2], s3 = acc[i][j][3];
                const float v0 = (ln0 == lc0) ? (1.0f - s0) : fmaxf(s0 - MARGIN, 0.0f);
                const float v1 = (ln0 == lc1) ? (1.0f - s1) : fmaxf(s1 - MARGIN, 0.0f);
                const float v2 = (ln1 == lc0) ? (1.0f - s2) : fmaxf(s2 - MARGIN, 0.0f);
                const float v3 = (ln1 == lc1) ? (1.0f - s3) : fmaxf(s3 - MARGIN, 0.0f);
                rs0 = fmaf(v0, pc0, rs0); rs0 = fmaf(v1, pc1, rs0);
                rs1 = fmaf(v2, pc0, rs1); rs1 = fmaf(v3, pc1, rs1);
            }
            tsum = fmaf(rs0, prow2[rl0], tsum);
            tsum = fmaf(rs1, prow2[rl1], tsum);
        }
    } else {
        // diagonal tiles (6%): full per-pair weight logic
#pragma unroll
        for (int i = 0; i < 4; i++) {
#pragma unroll
            for (int j = 0; j < 4; j++) {
                const int cl = 32 * wc + 8 * j + qc;
#pragma unroll
                for (int e = 0; e < 4; e++) {
                    const int rl = 64 * wr + 16 * i + gr + ((e >> 1) << 3);
                    const int cc = cl + (e & 1);
                    const float s = acc[i][j][e];
                    const float v = (lrow[rl] == lcol[cc]) ? (1.0f - s)
                                                           : fmaxf(s - MARGIN, 0.0f);
                    float w = prow2[rl] * pcol[cc];
                    if (cc == rl)     w *= 0.5f;
                    else if (cc < rl) w = 0.0f;
                    tsum = fmaf(v, w, tsum);
                }
            }
        }
    }

#pragma unroll
    for (int o = 16; o > 0; o >>= 1)
        tsum += __shfl_xor_sync(0xffffffffu, tsum, o);
    if (lid == 0) red[wid] = tsum;
    __syncthreads();
    if (tid == 0) {
        float bsum = 0.0f;
#pragma unroll
        for (int wv = 0; wv < 8; wv++) bsum += red[wv];
        atomicAdd(&g_acc, (double)bsum);
        __threadfence();
        const unsigned done = atomicAdd(&g_done, 1u);
        if (done == (unsigned)(GRID_GRAM - 1)) {
            __threadfence();
            out[0] = (float)(*((volatile double*)&g_acc) * (double)NPIX);
        }
    }
}

extern "C" void kernel_launch(void* const* d_in, const int* in_sizes, int n_in,
                              void* d_out, int out_size) {
    const float* emb = (const float*)d_in[0];
    const int*   lab = (const int*)d_in[1];
    float* out = (float*)d_out;

    prep_conv_kernel<<<CONV_BLOCKS + BATCH, 256>>>(emb, lab);
    gram_kernel<<<GRID_GRAM, 256>>>(lab, out);
}